// round 1
// baseline (speedup 1.0000x reference)
#include <cuda_runtime.h>
#include <math.h>

// Problem constants
#define B_    2
#define T_    2048
#define C_    1024
#define H_    16
#define D_    64
#define M_    (B_ * T_)          // 4096 rows
#define QKVN  (3 * H_ * D_)      // 3072

// Scratch (allocation-free rule: device globals)
__device__ float g_qkv[(size_t)M_ * QKVN];   // [4096, 3072]
__device__ float g_y  [(size_t)M_ * C_];     // [4096, 1024]

// ---------------------------------------------------------------------------
// sgemm128: C[M,N] = A[M,K] @ B[K,N], row-major, all dims divisible by tile.
// 128x128 block tile, BK=8, 256 threads, 8x8 per-thread micro-tile.
// ---------------------------------------------------------------------------
__global__ __launch_bounds__(256) void sgemm128(
    const float* __restrict__ A, const float* __restrict__ B,
    float* __restrict__ C, int M, int N, int K)
{
    const int BM = 128, BN = 128, BK = 8;
    __shared__ float As[BK * BM];   // transposed: As[k][m]
    __shared__ float Bs[BK * BN];   // Bs[k][n]

    const int tid = threadIdx.x;
    const int tx = tid & 15;        // 0..15 -> n
    const int ty = tid >> 4;        // 0..15 -> m
    const int m0 = blockIdx.y * BM;
    const int n0 = blockIdx.x * BN;

    // A-load mapping: one float4 per thread per k-tile
    const int arow = tid >> 1;          // 0..127
    const int acol = (tid & 1) * 4;     // 0 or 4
    // B-load mapping
    const int bk = tid >> 5;            // 0..7
    const int bc = (tid & 31) * 4;      // 0..124

    float acc[8][8];
    #pragma unroll
    for (int i = 0; i < 8; i++)
        #pragma unroll
        for (int j = 0; j < 8; j++) acc[i][j] = 0.f;

    for (int k0 = 0; k0 < K; k0 += BK) {
        float4 va = *reinterpret_cast<const float4*>(
            &A[(size_t)(m0 + arow) * K + k0 + acol]);
        As[(acol + 0) * BM + arow] = va.x;
        As[(acol + 1) * BM + arow] = va.y;
        As[(acol + 2) * BM + arow] = va.z;
        As[(acol + 3) * BM + arow] = va.w;
        *reinterpret_cast<float4*>(&Bs[bk * BN + bc]) =
            *reinterpret_cast<const float4*>(&B[(size_t)(k0 + bk) * N + n0 + bc]);
        __syncthreads();

        #pragma unroll
        for (int k = 0; k < BK; k++) {
            float a[8], b[8];
            *reinterpret_cast<float4*>(a)     = *reinterpret_cast<float4*>(&As[k * BM + ty * 8]);
            *reinterpret_cast<float4*>(a + 4) = *reinterpret_cast<float4*>(&As[k * BM + ty * 8 + 4]);
            *reinterpret_cast<float4*>(b)     = *reinterpret_cast<float4*>(&Bs[k * BN + tx * 8]);
            *reinterpret_cast<float4*>(b + 4) = *reinterpret_cast<float4*>(&Bs[k * BN + tx * 8 + 4]);
            #pragma unroll
            for (int i = 0; i < 8; i++)
                #pragma unroll
                for (int j = 0; j < 8; j++)
                    acc[i][j] += a[i] * b[j];
        }
        __syncthreads();
    }

    #pragma unroll
    for (int i = 0; i < 8; i++) {
        float* Cp = &C[(size_t)(m0 + ty * 8 + i) * N + n0 + tx * 8];
        *reinterpret_cast<float4*>(Cp)     = make_float4(acc[i][0], acc[i][1], acc[i][2], acc[i][3]);
        *reinterpret_cast<float4*>(Cp + 4) = make_float4(acc[i][4], acc[i][5], acc[i][6], acc[i][7]);
    }
}

// ---------------------------------------------------------------------------
// flash_attn: streaming causal attention with sink logit.
// qkv layout: row = b*T + t, cols [0:1024)=Q, [1024:2048)=K, [2048:3072)=V,
// each section h-major (h*64+d). y: [4096, 1024] row-major (t-major, h*64+d).
// Grid: (T/64, B*H). 256 threads = 8 warps; warp w owns query rows w*8..w*8+7.
// Each lane owns one key within the 32-key tile; P broadcast via shfl.
// ---------------------------------------------------------------------------
#define BQ   64
#define BKV  32
#define PAD  68   // floats per smem row: 16B-aligned, conflict-free (68 mod 32 = 4; /4=17 odd)

__global__ __launch_bounds__(256) void flash_attn(
    const float* __restrict__ qkv, const float* __restrict__ sink,
    float* __restrict__ y)
{
    __shared__ float Qs[BQ * PAD];
    __shared__ float Ks[BKV * PAD];
    __shared__ float Vs[BKV * PAD];

    const int tid  = threadIdx.x;
    const int lane = tid & 31;
    const int warp = tid >> 5;
    const int qt = blockIdx.x;             // query tile 0..31
    const int bh = blockIdx.y;             // 0..31
    const int b = bh / H_, h = bh % H_;
    const int q0 = qt * BQ;
    const float scale = rsqrtf((float)D_);
    const size_t rowbase = (size_t)b * T_;

    // Load Q tile [64 x 64]: 4 threads per row, 4 float4 each
    {
        const int r  = tid >> 2;           // 0..63
        const int c4 = (tid & 3) * 4;      // float4 index base
        const float* qp = &qkv[(rowbase + q0 + r) * QKVN + h * D_];
        #pragma unroll
        for (int i = 0; i < 4; i++)
            *reinterpret_cast<float4*>(&Qs[r * PAD + (c4 + i) * 4]) =
                *reinterpret_cast<const float4*>(qp + (c4 + i) * 4);
    }

    // Online softmax state per owned row; sink column: m=sink, l=1, acc=0
    float m[8], l[8], acc0[8], acc1[8];
    const float s_sink = sink[h];
    #pragma unroll
    for (int r = 0; r < 8; r++) { m[r] = s_sink; l[r] = 1.f; acc0[r] = 0.f; acc1[r] = 0.f; }

    __syncthreads();

    const int kend = q0 + BQ;   // exclusive causal bound for this tile
    for (int j0 = 0; j0 < kend; j0 += BKV) {
        // Load K,V tiles [32 x 64]: 8 threads per row, 2 float4 each
        {
            const int r  = tid >> 3;          // 0..31
            const int c4 = (tid & 7) * 2;     // float4 index base
            const float* kp = &qkv[(rowbase + j0 + r) * QKVN + H_ * D_ + h * D_];
            const float* vp = kp + H_ * D_;
            #pragma unroll
            for (int i = 0; i < 2; i++) {
                *reinterpret_cast<float4*>(&Ks[r * PAD + (c4 + i) * 4]) =
                    *reinterpret_cast<const float4*>(kp + (c4 + i) * 4);
                *reinterpret_cast<float4*>(&Vs[r * PAD + (c4 + i) * 4]) =
                    *reinterpret_cast<const float4*>(vp + (c4 + i) * 4);
            }
        }
        __syncthreads();

        const int kg = j0 + lane;   // this lane's key index
        #pragma unroll
        for (int r = 0; r < 8; r++) {
            const int qrow = warp * 8 + r;
            const int qg = q0 + qrow;

            // s = (Q[qrow] . K[lane]) * scale, causal-masked
            float s = 0.f;
            const float4* qp4 = reinterpret_cast<const float4*>(&Qs[qrow * PAD]);
            const float4* kp4 = reinterpret_cast<const float4*>(&Ks[lane * PAD]);
            #pragma unroll
            for (int d4 = 0; d4 < 16; d4++) {
                float4 qv = qp4[d4], kv = kp4[d4];
                s += qv.x * kv.x + qv.y * kv.y + qv.z * kv.z + qv.w * kv.w;
            }
            s *= scale;
            if (kg > qg) s = -1e30f;

            float tmax = s;
            #pragma unroll
            for (int o = 16; o > 0; o >>= 1)
                tmax = fmaxf(tmax, __shfl_xor_sync(0xffffffffu, tmax, o));
            const float mnew = fmaxf(m[r], tmax);
            float p = __expf(s - mnew);
            if (kg > qg) p = 0.f;
            const float corr = __expf(m[r] - mnew);
            float psum = p;
            #pragma unroll
            for (int o = 16; o > 0; o >>= 1)
                psum += __shfl_xor_sync(0xffffffffu, psum, o);
            l[r] = l[r] * corr + psum;
            m[r] = mnew;
            acc0[r] *= corr;
            acc1[r] *= corr;

            // acc[d] += sum_k p_k * V[k][d], d = lane and lane+32
            #pragma unroll
            for (int k = 0; k < BKV; k++) {
                const float pk = __shfl_sync(0xffffffffu, p, k);
                acc0[r] += pk * Vs[k * PAD + lane];
                acc1[r] += pk * Vs[k * PAD + 32 + lane];
            }
        }
        __syncthreads();
    }

    // Write y
    #pragma unroll
    for (int r = 0; r < 8; r++) {
        const int qrow = warp * 8 + r;
        const float inv = 1.f / l[r];
        float* yp = &y[(rowbase + q0 + qrow) * C_ + h * D_];
        yp[lane]      = acc0[r] * inv;
        yp[32 + lane] = acc1[r] * inv;
    }
}

// ---------------------------------------------------------------------------
extern "C" void kernel_launch(void* const* d_in, const int* in_sizes, int n_in,
                              void* d_out, int out_size)
{
    const float* x      = (const float*)d_in[0];   // [2,2048,1024]
    const float* w_qkv  = (const float*)d_in[1];   // [1024,3072]
    const float* w_proj = (const float*)d_in[2];   // [1024,1024]
    const float* sink   = (const float*)d_in[3];   // [16]
    float* out = (float*)d_out;                    // [4096,1024]

    float *qkv, *yb;
    cudaGetSymbolAddress((void**)&qkv, g_qkv);
    cudaGetSymbolAddress((void**)&yb,  g_y);

    // 1) qkv = x @ w_qkv : [4096,1024]@[1024,3072]
    sgemm128<<<dim3(QKVN / 128, M_ / 128), 256>>>(x, w_qkv, qkv, M_, QKVN, C_);
    // 2) attention (causal + sink) -> y [4096,1024]
    flash_attn<<<dim3(T_ / BQ, B_ * H_), 256>>>(qkv, sink, yb);
    // 3) out = y @ w_proj : [4096,1024]@[1024,1024]
    sgemm128<<<dim3(C_ / 128, M_ / 128), 256>>>(yb, w_proj, out, M_, C_, C_);
}

// round 2
// speedup vs baseline: 2.9087x; 2.9087x over previous
#include <cuda_runtime.h>
#include <math.h>
#include <stdint.h>

// Problem constants
#define B_    2
#define T_    2048
#define C_    1024
#define H_    16
#define D_    64
#define M_    (B_ * T_)          // 4096
#define QKVN  (3 * H_ * D_)      // 3072

// Scratch (allocation-free rule: device globals)
__device__ float g_qkv[(size_t)M_ * QKVN];
__device__ float g_y  [(size_t)M_ * C_];

// ---------------------------------------------------------------------------
// tf32 helpers
// ---------------------------------------------------------------------------
__device__ __forceinline__ uint32_t f2tf(float x) {
    uint32_t r;
    asm("cvt.rna.tf32.f32 %0, %1;" : "=r"(r) : "f"(x));
    return r;
}

__device__ __forceinline__ void mma_tf32(float c[4], const uint32_t a[4],
                                         const uint32_t b[2]) {
    asm volatile(
        "mma.sync.aligned.m16n8k8.row.col.f32.tf32.tf32.f32 "
        "{%0,%1,%2,%3}, {%4,%5,%6,%7}, {%8,%9}, {%0,%1,%2,%3};\n"
        : "+f"(c[0]), "+f"(c[1]), "+f"(c[2]), "+f"(c[3])
        : "r"(a[0]), "r"(a[1]), "r"(a[2]), "r"(a[3]), "r"(b[0]), "r"(b[1]));
}

// ---------------------------------------------------------------------------
// gemm_tf32: C[M,N] = A[M,K] @ B[K,N], row-major. 128x128 tile, BK=16,
// 256 threads (8 warps, 4x2), warp tile 32x64, mma.m16n8k8.tf32.
// Smem stride 136 (== 8 mod 32) -> conflict-free fragment LDS.
// ---------------------------------------------------------------------------
#define GSTR 136

__global__ __launch_bounds__(256) void gemm_tf32(
    const float* __restrict__ A, const float* __restrict__ Bm,
    float* __restrict__ Cm, int M, int N, int K)
{
    __shared__ uint32_t As[2][16 * GSTR];   // As[k][m]
    __shared__ uint32_t Bs[2][16 * GSTR];   // Bs[k][n]

    const int tid  = threadIdx.x;
    const int lane = tid & 31;
    const int warp = tid >> 5;
    const int wm = warp >> 1;               // 0..3
    const int wn = warp & 1;                // 0..1
    const int g = lane >> 2, t = lane & 3;
    const int m0 = blockIdx.y * 128;
    const int n0 = blockIdx.x * 128;
    const int nk = K / 16;

    float4 ra[2], rb[2];

    // ---- fetch tile 0 from global
    #pragma unroll
    for (int i = 0; i < 2; i++) {
        const int F = tid + 256 * i;
        const int ar = F & 127, ac = (F >> 7) * 4;
        ra[i] = *reinterpret_cast<const float4*>(&A[(size_t)(m0 + ar) * K + ac]);
        const int br = F >> 5, bc = (F & 31) * 4;
        rb[i] = *reinterpret_cast<const float4*>(&Bm[(size_t)br * N + n0 + bc]);
    }
    // ---- store buffer 0 (tf32-converted)
    #pragma unroll
    for (int i = 0; i < 2; i++) {
        const int F = tid + 256 * i;
        const int ar = F & 127, ac = (F >> 7) * 4;
        As[0][(ac + 0) * GSTR + ar] = f2tf(ra[i].x);
        As[0][(ac + 1) * GSTR + ar] = f2tf(ra[i].y);
        As[0][(ac + 2) * GSTR + ar] = f2tf(ra[i].z);
        As[0][(ac + 3) * GSTR + ar] = f2tf(ra[i].w);
        const int br = F >> 5, bc = (F & 31) * 4;
        uint32_t* bp = &Bs[0][br * GSTR + bc];
        bp[0] = f2tf(rb[i].x); bp[1] = f2tf(rb[i].y);
        bp[2] = f2tf(rb[i].z); bp[3] = f2tf(rb[i].w);
    }
    __syncthreads();

    float acc[2][8][4];
    #pragma unroll
    for (int mt = 0; mt < 2; mt++)
        #pragma unroll
        for (int nt = 0; nt < 8; nt++)
            #pragma unroll
            for (int j = 0; j < 4; j++) acc[mt][nt][j] = 0.f;

    for (int kt = 0; kt < nk; kt++) {
        const int cur = kt & 1;
        if (kt + 1 < nk) {
            const int k0 = (kt + 1) * 16;
            #pragma unroll
            for (int i = 0; i < 2; i++) {
                const int F = tid + 256 * i;
                const int ar = F & 127, ac = (F >> 7) * 4;
                ra[i] = *reinterpret_cast<const float4*>(
                    &A[(size_t)(m0 + ar) * K + k0 + ac]);
                const int br = F >> 5, bc = (F & 31) * 4;
                rb[i] = *reinterpret_cast<const float4*>(
                    &Bm[(size_t)(k0 + br) * N + n0 + bc]);
            }
        }
        // ---- compute on current buffer
        #pragma unroll
        for (int kk = 0; kk < 16; kk += 8) {
            uint32_t af[2][4], bf[8][2];
            #pragma unroll
            for (int mt = 0; mt < 2; mt++) {
                const int mr = wm * 32 + mt * 16 + g;
                af[mt][0] = As[cur][(kk + t)     * GSTR + mr];
                af[mt][1] = As[cur][(kk + t)     * GSTR + mr + 8];
                af[mt][2] = As[cur][(kk + t + 4) * GSTR + mr];
                af[mt][3] = As[cur][(kk + t + 4) * GSTR + mr + 8];
            }
            #pragma unroll
            for (int nt = 0; nt < 8; nt++) {
                const int nc = wn * 64 + nt * 8 + g;
                bf[nt][0] = Bs[cur][(kk + t)     * GSTR + nc];
                bf[nt][1] = Bs[cur][(kk + t + 4) * GSTR + nc];
            }
            #pragma unroll
            for (int mt = 0; mt < 2; mt++)
                #pragma unroll
                for (int nt = 0; nt < 8; nt++)
                    mma_tf32(acc[mt][nt], af[mt], bf[nt]);
        }
        if (kt + 1 < nk) {
            const int nxt = (kt + 1) & 1;
            #pragma unroll
            for (int i = 0; i < 2; i++) {
                const int F = tid + 256 * i;
                const int ar = F & 127, ac = (F >> 7) * 4;
                As[nxt][(ac + 0) * GSTR + ar] = f2tf(ra[i].x);
                As[nxt][(ac + 1) * GSTR + ar] = f2tf(ra[i].y);
                As[nxt][(ac + 2) * GSTR + ar] = f2tf(ra[i].z);
                As[nxt][(ac + 3) * GSTR + ar] = f2tf(ra[i].w);
                const int br = F >> 5, bc = (F & 31) * 4;
                uint32_t* bp = &Bs[nxt][br * GSTR + bc];
                bp[0] = f2tf(rb[i].x); bp[1] = f2tf(rb[i].y);
                bp[2] = f2tf(rb[i].z); bp[3] = f2tf(rb[i].w);
            }
        }
        __syncthreads();
    }

    // ---- epilogue
    #pragma unroll
    for (int mt = 0; mt < 2; mt++) {
        const int r0 = m0 + wm * 32 + mt * 16 + g;
        #pragma unroll
        for (int nt = 0; nt < 8; nt++) {
            const int c0 = n0 + wn * 64 + nt * 8 + 2 * t;
            *reinterpret_cast<float2*>(&Cm[(size_t)r0 * N + c0]) =
                make_float2(acc[mt][nt][0], acc[mt][nt][1]);
            *reinterpret_cast<float2*>(&Cm[(size_t)(r0 + 8) * N + c0]) =
                make_float2(acc[mt][nt][2], acc[mt][nt][3]);
        }
    }
}

// ---------------------------------------------------------------------------
// attn_tf32: tensor-core flash attention with sink logit.
// Grid (T/64, B*H). 128 threads = 4 warps; warp w owns query rows w*16..+15.
// BKV=32 keys per tile. S and P.V via mma.m16n8k8.tf32; P staged through
// per-warp smem (stride 36 -> conflict-free A-fragment reloads).
// ---------------------------------------------------------------------------
#define KSTR 68
#define VSTR 72
#define PSTR 36

__global__ __launch_bounds__(128) void attn_tf32(
    const float* __restrict__ qkv, const float* __restrict__ sink,
    float* __restrict__ y)
{
    __shared__ uint32_t Ks[32 * KSTR];
    __shared__ uint32_t Vs[32 * VSTR];
    __shared__ uint32_t Ps[4 * 16 * PSTR];

    const int tid  = threadIdx.x;
    const int lane = tid & 31;
    const int warp = tid >> 5;
    const int g = lane >> 2, t = lane & 3;
    const int qt = blockIdx.x;
    const int bh = blockIdx.y;
    const int b = bh >> 4, h = bh & 15;     // H_ = 16
    const int q0 = qt * 64;
    const size_t rowbase = (size_t)b * T_;
    const float scale = 0.125f;             // 1/sqrt(64)

    const int rg0 = q0 + warp * 16 + g;     // first owned row
    const int rg1 = rg0 + 8;                // second owned row

    // ---- Q fragments, register-resident, scale folded in
    uint32_t qa[8][4];
    {
        const float* qp0 = &qkv[(rowbase + rg0) * QKVN + h * D_];
        const float* qp8 = qp0 + (size_t)8 * QKVN;
        #pragma unroll
        for (int ks = 0; ks < 8; ks++) {
            qa[ks][0] = f2tf(qp0[ks * 8 + t]       * scale);
            qa[ks][1] = f2tf(qp8[ks * 8 + t]       * scale);
            qa[ks][2] = f2tf(qp0[ks * 8 + t + 4]   * scale);
            qa[ks][3] = f2tf(qp8[ks * 8 + t + 4]   * scale);
        }
    }

    // ---- online softmax state (sink column: m = sink, l = 1, acc = 0)
    float m0v = sink[h], m1v = m0v;
    float l0 = 1.f, l1 = 1.f;
    float oacc[8][4];
    #pragma unroll
    for (int dt = 0; dt < 8; dt++)
        #pragma unroll
        for (int j = 0; j < 4; j++) oacc[dt][j] = 0.f;

    uint32_t* Pw = &Ps[warp * 16 * PSTR];
    const int kend = q0 + 64;

    for (int j0 = 0; j0 < kend; j0 += 32) {
        // ---- load K,V tile [32 x 64] into smem (tf32)
        #pragma unroll
        for (int i = 0; i < 4; i++) {
            const int F = tid + 128 * i;
            const int r = F >> 4, c4 = (F & 15) * 4;
            const float* kp = &qkv[(rowbase + j0 + r) * QKVN + H_ * D_ + h * D_ + c4];
            const float* vp = kp + H_ * D_;
            const float4 kv = *reinterpret_cast<const float4*>(kp);
            const float4 vv = *reinterpret_cast<const float4*>(vp);
            uint4 ku = make_uint4(f2tf(kv.x), f2tf(kv.y), f2tf(kv.z), f2tf(kv.w));
            uint4 vu = make_uint4(f2tf(vv.x), f2tf(vv.y), f2tf(vv.z), f2tf(vv.w));
            *reinterpret_cast<uint4*>(&Ks[r * KSTR + c4]) = ku;
            *reinterpret_cast<uint4*>(&Vs[r * VSTR + c4]) = vu;
        }
        __syncthreads();

        // ---- S = (Q*scale) . K^T   [16 x 32 per warp]
        float sacc[4][4];
        #pragma unroll
        for (int nt = 0; nt < 4; nt++)
            #pragma unroll
            for (int j = 0; j < 4; j++) sacc[nt][j] = 0.f;

        #pragma unroll
        for (int ks = 0; ks < 8; ks++) {
            #pragma unroll
            for (int nt = 0; nt < 4; nt++) {
                uint32_t bb[2];
                bb[0] = Ks[(nt * 8 + g) * KSTR + ks * 8 + t];
                bb[1] = Ks[(nt * 8 + g) * KSTR + ks * 8 + t + 4];
                mma_tf32(sacc[nt], qa[ks], bb);
            }
        }

        // ---- causal mask (only needed on the last two tiles)
        if (j0 >= q0) {
            #pragma unroll
            for (int nt = 0; nt < 4; nt++) {
                const int cg = j0 + nt * 8 + 2 * t;
                if (cg     > rg0) sacc[nt][0] = -1e30f;
                if (cg + 1 > rg0) sacc[nt][1] = -1e30f;
                if (cg     > rg1) sacc[nt][2] = -1e30f;
                if (cg + 1 > rg1) sacc[nt][3] = -1e30f;
            }
        }

        // ---- row maxima (in-thread + quad shfl)
        float rmax0 = -1e30f, rmax1 = -1e30f;
        #pragma unroll
        for (int nt = 0; nt < 4; nt++) {
            rmax0 = fmaxf(rmax0, fmaxf(sacc[nt][0], sacc[nt][1]));
            rmax1 = fmaxf(rmax1, fmaxf(sacc[nt][2], sacc[nt][3]));
        }
        rmax0 = fmaxf(rmax0, __shfl_xor_sync(0xffffffffu, rmax0, 1));
        rmax0 = fmaxf(rmax0, __shfl_xor_sync(0xffffffffu, rmax0, 2));
        rmax1 = fmaxf(rmax1, __shfl_xor_sync(0xffffffffu, rmax1, 1));
        rmax1 = fmaxf(rmax1, __shfl_xor_sync(0xffffffffu, rmax1, 2));

        const float mn0 = fmaxf(m0v, rmax0);
        const float mn1 = fmaxf(m1v, rmax1);
        const float corr0 = __expf(m0v - mn0);
        const float corr1 = __expf(m1v - mn1);
        m0v = mn0; m1v = mn1;

        // ---- P = exp(S - m), stage to smem as tf32, accumulate row sums
        float ps0 = 0.f, ps1 = 0.f;
        #pragma unroll
        for (int nt = 0; nt < 4; nt++) {
            const float p0 = __expf(sacc[nt][0] - mn0);
            const float p1 = __expf(sacc[nt][1] - mn0);
            const float p2 = __expf(sacc[nt][2] - mn1);
            const float p3 = __expf(sacc[nt][3] - mn1);
            ps0 += p0 + p1;
            ps1 += p2 + p3;
            *reinterpret_cast<uint2*>(&Pw[g * PSTR + nt * 8 + 2 * t]) =
                make_uint2(f2tf(p0), f2tf(p1));
            *reinterpret_cast<uint2*>(&Pw[(g + 8) * PSTR + nt * 8 + 2 * t]) =
                make_uint2(f2tf(p2), f2tf(p3));
        }
        ps0 += __shfl_xor_sync(0xffffffffu, ps0, 1);
        ps0 += __shfl_xor_sync(0xffffffffu, ps0, 2);
        ps1 += __shfl_xor_sync(0xffffffffu, ps1, 1);
        ps1 += __shfl_xor_sync(0xffffffffu, ps1, 2);
        l0 = l0 * corr0 + ps0;
        l1 = l1 * corr1 + ps1;

        // ---- rescale output accumulators
        #pragma unroll
        for (int dt = 0; dt < 8; dt++) {
            oacc[dt][0] *= corr0; oacc[dt][1] *= corr0;
            oacc[dt][2] *= corr1; oacc[dt][3] *= corr1;
        }

        __syncwarp();

        // ---- O += P . V
        #pragma unroll
        for (int ks2 = 0; ks2 < 4; ks2++) {
            uint32_t pa[4];
            pa[0] = Pw[g       * PSTR + ks2 * 8 + t];
            pa[1] = Pw[(g + 8) * PSTR + ks2 * 8 + t];
            pa[2] = Pw[g       * PSTR + ks2 * 8 + t + 4];
            pa[3] = Pw[(g + 8) * PSTR + ks2 * 8 + t + 4];
            #pragma unroll
            for (int dt = 0; dt < 8; dt++) {
                uint32_t vb[2];
                vb[0] = Vs[(ks2 * 8 + t)     * VSTR + dt * 8 + g];
                vb[1] = Vs[(ks2 * 8 + t + 4) * VSTR + dt * 8 + g];
                mma_tf32(oacc[dt], pa, vb);
            }
        }
        __syncthreads();
    }

    // ---- write y
    const float inv0 = 1.f / l0, inv1 = 1.f / l1;
    float* yp0 = &y[(rowbase + rg0) * C_ + h * D_];
    float* yp1 = &y[(rowbase + rg1) * C_ + h * D_];
    #pragma unroll
    for (int dt = 0; dt < 8; dt++) {
        const int c = dt * 8 + 2 * t;
        *reinterpret_cast<float2*>(yp0 + c) =
            make_float2(oacc[dt][0] * inv0, oacc[dt][1] * inv0);
        *reinterpret_cast<float2*>(yp1 + c) =
            make_float2(oacc[dt][2] * inv1, oacc[dt][3] * inv1);
    }
}

// ---------------------------------------------------------------------------
extern "C" void kernel_launch(void* const* d_in, const int* in_sizes, int n_in,
                              void* d_out, int out_size)
{
    const float* x      = (const float*)d_in[0];   // [2,2048,1024]
    const float* w_qkv  = (const float*)d_in[1];   // [1024,3072]
    const float* w_proj = (const float*)d_in[2];   // [1024,1024]
    const float* sink   = (const float*)d_in[3];   // [16]
    float* out = (float*)d_out;                    // [4096,1024]

    float *qkv, *yb;
    cudaGetSymbolAddress((void**)&qkv, g_qkv);
    cudaGetSymbolAddress((void**)&yb,  g_y);

    // 1) qkv = x @ w_qkv
    gemm_tf32<<<dim3(QKVN / 128, M_ / 128), 256>>>(x, w_qkv, qkv, M_, QKVN, C_);
    // 2) attention (causal + sink)
    attn_tf32<<<dim3(T_ / 64, B_ * H_), 128>>>(qkv, sink, yb);
    // 3) out = y @ w_proj
    gemm_tf32<<<dim3(C_ / 128, M_ / 128), 256>>>(yb, w_proj, out, M_, C_, C_);
}

// round 3
// speedup vs baseline: 6.2963x; 2.1646x over previous
#include <cuda_runtime.h>
#include <cuda_fp16.h>
#include <math.h>
#include <stdint.h>

// Problem constants
#define B_    2
#define T_    2048
#define C_    1024
#define H_    16
#define D_    64
#define M_    (B_ * T_)          // 4096
#define QKVN  (3 * H_ * D_)      // 3072

// Scratch (allocation-free rule: device globals) — fp16
__device__ __half g_qkv[(size_t)M_ * QKVN];
__device__ __half g_y  [(size_t)M_ * C_];

// ---------------------------------------------------------------------------
// helpers
// ---------------------------------------------------------------------------
__device__ __forceinline__ uint32_t pack2(float x, float y) {
    __half2 h = __floats2half2_rn(x, y);
    return *reinterpret_cast<uint32_t*>(&h);
}
__device__ __forceinline__ void mma_f16(float c[4], const uint32_t a[4],
                                        const uint32_t b[2]) {
    asm volatile(
        "mma.sync.aligned.m16n8k16.row.col.f32.f16.f16.f32 "
        "{%0,%1,%2,%3}, {%4,%5,%6,%7}, {%8,%9}, {%0,%1,%2,%3};\n"
        : "+f"(c[0]), "+f"(c[1]), "+f"(c[2]), "+f"(c[3])
        : "r"(a[0]), "r"(a[1]), "r"(a[2]), "r"(a[3]), "r"(b[0]), "r"(b[1]));
}
__device__ __forceinline__ void ldm_x4(uint32_t r[4], uint32_t addr) {
    asm volatile("ldmatrix.sync.aligned.m8n8.x4.shared.b16 {%0,%1,%2,%3}, [%4];"
        : "=r"(r[0]), "=r"(r[1]), "=r"(r[2]), "=r"(r[3]) : "r"(addr));
}
__device__ __forceinline__ void ldm_x4t(uint32_t r[4], uint32_t addr) {
    asm volatile("ldmatrix.sync.aligned.m8n8.x4.trans.shared.b16 {%0,%1,%2,%3}, [%4];"
        : "=r"(r[0]), "=r"(r[1]), "=r"(r[2]), "=r"(r[3]) : "r"(addr));
}

// A-tile source: fp32 -> convert; fp16 -> passthrough
__device__ __forceinline__ uint2 ldA4(const float* p) {
    float4 v = *reinterpret_cast<const float4*>(p);
    return make_uint2(pack2(v.x, v.y), pack2(v.z, v.w));
}
__device__ __forceinline__ uint2 ldA4(const __half* p) {
    return *reinterpret_cast<const uint2*>(p);
}
// C-tile sink
__device__ __forceinline__ void stC2(float* p, float a, float b) {
    *reinterpret_cast<float2*>(p) = make_float2(a, b);
}
__device__ __forceinline__ void stC2(__half* p, float a, float b) {
    *reinterpret_cast<__half2*>(p) = __floats2half2_rn(a, b);
}

// ---------------------------------------------------------------------------
// gemm_f16: C[M,N] = A[M,K] @ B[K,N]. 128x128 tile, BK=16, 256 threads
// (8 warps 4x2, warp tile 32x64), mma.m16n8k16.f16, ldmatrix fragments,
// double-buffered smem. A source fp32 or fp16; B fp32; C fp32 or fp16.
// ---------------------------------------------------------------------------
#define ASTR 24    // halves per A smem row (16 + 8 pad) = 48B (odd x 16B)
#define BSTR 136   // halves per B smem row (128 + 8)   = 272B (odd x 16B)

template <typename TA, typename TC>
__global__ __launch_bounds__(256) void gemm_f16(
    const TA* __restrict__ A, const float* __restrict__ Bm,
    TC* __restrict__ Cm, int M, int N, int K)
{
    __shared__ __half As[2][128 * ASTR];
    __shared__ __half Bs[2][16 * BSTR];

    const int tid  = threadIdx.x;
    const int lane = tid & 31;
    const int warp = tid >> 5;
    const int wm = warp >> 1, wn = warp & 1;
    const int g = lane >> 2, t = lane & 3;
    const int m0 = blockIdx.y * 128;
    const int n0 = blockIdx.x * 128;
    const int nk = K / 16;

    // global load mappings (2 chunks of 4 k-elems each per thread)
    const int ar = tid >> 2, ac = (tid & 3) * 4;   // A: rows ar, ar+64
    const int br = tid >> 5, bc = (tid & 31) * 4;  // B: rows br, br+8

    // ldmatrix addresses (buffer 0)
    uint32_t aAddr[2], bAddr[4];
    {
        #pragma unroll
        for (int mt = 0; mt < 2; mt++) {
            const int row = wm * 32 + mt * 16 + (lane & 15);
            const int col = (lane >> 4) * 8;
            aAddr[mt] = (uint32_t)__cvta_generic_to_shared(&As[0][row * ASTR + col]);
        }
        #pragma unroll
        for (int ntp = 0; ntp < 4; ntp++) {
            const int krow = ((lane >> 3) & 1) * 8 + (lane & 7);
            const int ncol = wn * 64 + ntp * 16 + (lane >> 4) * 8;
            bAddr[ntp] = (uint32_t)__cvta_generic_to_shared(&Bs[0][krow * BSTR + ncol]);
        }
    }
    const uint32_t ABUF = 128 * ASTR * 2;   // bytes per buffer
    const uint32_t BBUF = 16 * BSTR * 2;

    // ---- tile 0: fetch + store
    uint2 pa0 = ldA4(&A[(size_t)(m0 + ar) * K + ac]);
    uint2 pa1 = ldA4(&A[(size_t)(m0 + ar + 64) * K + ac]);
    float4 fb0 = *reinterpret_cast<const float4*>(&Bm[(size_t)br * N + n0 + bc]);
    float4 fb1 = *reinterpret_cast<const float4*>(&Bm[(size_t)(br + 8) * N + n0 + bc]);
    *reinterpret_cast<uint2*>(&As[0][ar * ASTR + ac]) = pa0;
    *reinterpret_cast<uint2*>(&As[0][(ar + 64) * ASTR + ac]) = pa1;
    *reinterpret_cast<uint2*>(&Bs[0][br * BSTR + bc]) =
        make_uint2(pack2(fb0.x, fb0.y), pack2(fb0.z, fb0.w));
    *reinterpret_cast<uint2*>(&Bs[0][(br + 8) * BSTR + bc]) =
        make_uint2(pack2(fb1.x, fb1.y), pack2(fb1.z, fb1.w));
    __syncthreads();

    float acc[2][8][4];
    #pragma unroll
    for (int mt = 0; mt < 2; mt++)
        #pragma unroll
        for (int nt = 0; nt < 8; nt++)
            #pragma unroll
            for (int j = 0; j < 4; j++) acc[mt][nt][j] = 0.f;

    for (int kt = 0; kt < nk; kt++) {
        const int cur = kt & 1;
        // prefetch next tile
        if (kt + 1 < nk) {
            const int k0 = (kt + 1) * 16;
            pa0 = ldA4(&A[(size_t)(m0 + ar) * K + k0 + ac]);
            pa1 = ldA4(&A[(size_t)(m0 + ar + 64) * K + k0 + ac]);
            fb0 = *reinterpret_cast<const float4*>(&Bm[(size_t)(k0 + br) * N + n0 + bc]);
            fb1 = *reinterpret_cast<const float4*>(&Bm[(size_t)(k0 + br + 8) * N + n0 + bc]);
        }
        // fragments via ldmatrix
        uint32_t af[2][4], bf[4][4];
        ldm_x4(af[0], aAddr[0] + cur * ABUF);
        ldm_x4(af[1], aAddr[1] + cur * ABUF);
        #pragma unroll
        for (int ntp = 0; ntp < 4; ntp++)
            ldm_x4t(bf[ntp], bAddr[ntp] + cur * BBUF);
        // 16 mma
        #pragma unroll
        for (int mt = 0; mt < 2; mt++)
            #pragma unroll
            for (int nt = 0; nt < 8; nt++)
                mma_f16(acc[mt][nt], af[mt], &bf[nt >> 1][(nt & 1) * 2]);
        // store next
        if (kt + 1 < nk) {
            const int nxt = (kt + 1) & 1;
            *reinterpret_cast<uint2*>(&As[nxt][ar * ASTR + ac]) = pa0;
            *reinterpret_cast<uint2*>(&As[nxt][(ar + 64) * ASTR + ac]) = pa1;
            *reinterpret_cast<uint2*>(&Bs[nxt][br * BSTR + bc]) =
                make_uint2(pack2(fb0.x, fb0.y), pack2(fb0.z, fb0.w));
            *reinterpret_cast<uint2*>(&Bs[nxt][(br + 8) * BSTR + bc]) =
                make_uint2(pack2(fb1.x, fb1.y), pack2(fb1.z, fb1.w));
        }
        __syncthreads();
    }

    // epilogue
    #pragma unroll
    for (int mt = 0; mt < 2; mt++) {
        const int r0 = m0 + wm * 32 + mt * 16 + g;
        #pragma unroll
        for (int nt = 0; nt < 8; nt++) {
            const int c0 = n0 + wn * 64 + nt * 8 + 2 * t;
            stC2(&Cm[(size_t)r0 * N + c0],       acc[mt][nt][0], acc[mt][nt][1]);
            stC2(&Cm[(size_t)(r0 + 8) * N + c0], acc[mt][nt][2], acc[mt][nt][3]);
        }
    }
}

// ---------------------------------------------------------------------------
// attn_f16: tensor-core flash attention, sink logit, P kept in registers.
// Grid (T/64, B*H), 128 threads = 4 warps; warp owns 16 query rows.
// BKV=32. S and P.V via mma.m16n8k16.f16 + ldmatrix.
// ---------------------------------------------------------------------------
#define KVSTR 72   // halves per KV smem row (64 + 8) = 144B (odd x 16B)

__global__ __launch_bounds__(128) void attn_f16(
    const __half* __restrict__ qkv, const float* __restrict__ sink,
    __half* __restrict__ y)
{
    __shared__ __half Ks[32 * KVSTR];
    __shared__ __half Vs[32 * KVSTR];

    const int tid  = threadIdx.x;
    const int lane = tid & 31;
    const int warp = tid >> 5;
    const int g = lane >> 2, t = lane & 3;
    const int qt = blockIdx.x;
    const int bh = blockIdx.y;
    const int b = bh >> 4, h = bh & 15;
    const int q0 = qt * 64;
    const size_t rowbase = (size_t)b * T_;

    const int rg0 = q0 + warp * 16 + g;
    const int rg1 = rg0 + 8;

    // ---- Q fragments (register-resident, scale 1/8 folded; exact in fp16)
    uint32_t qa[4][4];
    {
        const __half2 sc = __floats2half2_rn(0.125f, 0.125f);
        const __half2* qp0 = reinterpret_cast<const __half2*>(
            &qkv[(rowbase + rg0) * QKVN + h * D_]);
        const __half2* qp8 = qp0 + (size_t)8 * QKVN / 2;
        #pragma unroll
        for (int ks = 0; ks < 4; ks++) {
            __half2 v0 = __hmul2(qp0[8 * ks + t], sc);
            __half2 v1 = __hmul2(qp8[8 * ks + t], sc);
            __half2 v2 = __hmul2(qp0[8 * ks + t + 4], sc);
            __half2 v3 = __hmul2(qp8[8 * ks + t + 4], sc);
            qa[ks][0] = *reinterpret_cast<uint32_t*>(&v0);
            qa[ks][1] = *reinterpret_cast<uint32_t*>(&v1);
            qa[ks][2] = *reinterpret_cast<uint32_t*>(&v2);
            qa[ks][3] = *reinterpret_cast<uint32_t*>(&v3);
        }
    }

    // ldmatrix base addresses
    uint32_t addrK[2], addrV[4];
    {
        const int kvK = ((lane >> 4) & 1) * 8 + (lane & 7);
        const int dK  = ((lane >> 3) & 1) * 8;
        addrK[0] = (uint32_t)__cvta_generic_to_shared(&Ks[kvK * KVSTR + dK]);
        addrK[1] = addrK[0] + 16 * KVSTR * 2;     // +16 kv rows
        const int kvV = ((lane >> 3) & 1) * 8 + (lane & 7);
        #pragma unroll
        for (int dtp = 0; dtp < 4; dtp++) {
            const int dV = dtp * 16 + ((lane >> 4) & 1) * 8;
            addrV[dtp] = (uint32_t)__cvta_generic_to_shared(&Vs[kvV * KVSTR + dV]);
        }
    }

    // online softmax state (sink: m = sink_logit, l = 1, acc = 0)
    float m0v = sink[h], m1v = m0v;
    float l0 = 1.f, l1 = 1.f;
    float oacc[8][4];
    #pragma unroll
    for (int dt = 0; dt < 8; dt++)
        #pragma unroll
        for (int j = 0; j < 4; j++) oacc[dt][j] = 0.f;

    const int kend = q0 + 64;
    for (int j0 = 0; j0 < kend; j0 += 32) {
        // ---- load K,V tile [32 x 64] halves (uint2 = 4 halves per store)
        #pragma unroll
        for (int i = 0; i < 4; i++) {
            const int F = tid + 128 * i;
            const int r = F >> 4, ch = (F & 15) * 4;
            const size_t gidx = (rowbase + j0 + r) * QKVN + H_ * D_ + h * D_ + ch;
            *reinterpret_cast<uint2*>(&Ks[r * KVSTR + ch]) =
                *reinterpret_cast<const uint2*>(&qkv[gidx]);
            *reinterpret_cast<uint2*>(&Vs[r * KVSTR + ch]) =
                *reinterpret_cast<const uint2*>(&qkv[gidx + H_ * D_]);
        }
        __syncthreads();

        // ---- S = (Q/8) . K^T    [16 x 32 per warp]
        float sacc[4][4];
        #pragma unroll
        for (int nt = 0; nt < 4; nt++)
            #pragma unroll
            for (int j = 0; j < 4; j++) sacc[nt][j] = 0.f;
        #pragma unroll
        for (int ks = 0; ks < 4; ks++) {
            uint32_t bk0[4], bk1[4];
            ldm_x4(bk0, addrK[0] + ks * 32);
            ldm_x4(bk1, addrK[1] + ks * 32);
            mma_f16(sacc[0], qa[ks], &bk0[0]);
            mma_f16(sacc[1], qa[ks], &bk0[2]);
            mma_f16(sacc[2], qa[ks], &bk1[0]);
            mma_f16(sacc[3], qa[ks], &bk1[2]);
        }

        // ---- causal mask (last two tiles only)
        if (j0 >= q0) {
            #pragma unroll
            for (int nt = 0; nt < 4; nt++) {
                const int cg = j0 + nt * 8 + 2 * t;
                if (cg     > rg0) sacc[nt][0] = -1e30f;
                if (cg + 1 > rg0) sacc[nt][1] = -1e30f;
                if (cg     > rg1) sacc[nt][2] = -1e30f;
                if (cg + 1 > rg1) sacc[nt][3] = -1e30f;
            }
        }

        // ---- row maxima
        float rmax0 = -1e30f, rmax1 = -1e30f;
        #pragma unroll
        for (int nt = 0; nt < 4; nt++) {
            rmax0 = fmaxf(rmax0, fmaxf(sacc[nt][0], sacc[nt][1]));
            rmax1 = fmaxf(rmax1, fmaxf(sacc[nt][2], sacc[nt][3]));
        }
        rmax0 = fmaxf(rmax0, __shfl_xor_sync(0xffffffffu, rmax0, 1));
        rmax0 = fmaxf(rmax0, __shfl_xor_sync(0xffffffffu, rmax0, 2));
        rmax1 = fmaxf(rmax1, __shfl_xor_sync(0xffffffffu, rmax1, 1));
        rmax1 = fmaxf(rmax1, __shfl_xor_sync(0xffffffffu, rmax1, 2));

        const float mn0 = fmaxf(m0v, rmax0);
        const float mn1 = fmaxf(m1v, rmax1);
        const float corr0 = __expf(m0v - mn0);
        const float corr1 = __expf(m1v - mn1);
        m0v = mn0; m1v = mn1;

        // ---- P = exp(S - m); pack directly into mma A-fragments
        float p[4][4];
        float ps0 = 0.f, ps1 = 0.f;
        #pragma unroll
        for (int nt = 0; nt < 4; nt++) {
            p[nt][0] = __expf(sacc[nt][0] - mn0);
            p[nt][1] = __expf(sacc[nt][1] - mn0);
            p[nt][2] = __expf(sacc[nt][2] - mn1);
            p[nt][3] = __expf(sacc[nt][3] - mn1);
            ps0 += p[nt][0] + p[nt][1];
            ps1 += p[nt][2] + p[nt][3];
        }
        ps0 += __shfl_xor_sync(0xffffffffu, ps0, 1);
        ps0 += __shfl_xor_sync(0xffffffffu, ps0, 2);
        ps1 += __shfl_xor_sync(0xffffffffu, ps1, 1);
        ps1 += __shfl_xor_sync(0xffffffffu, ps1, 2);
        l0 = l0 * corr0 + ps0;
        l1 = l1 * corr1 + ps1;

        uint32_t pa[2][4];
        #pragma unroll
        for (int kg = 0; kg < 2; kg++) {
            pa[kg][0] = pack2(p[kg * 2][0], p[kg * 2][1]);
            pa[kg][1] = pack2(p[kg * 2][2], p[kg * 2][3]);
            pa[kg][2] = pack2(p[kg * 2 + 1][0], p[kg * 2 + 1][1]);
            pa[kg][3] = pack2(p[kg * 2 + 1][2], p[kg * 2 + 1][3]);
        }

        // ---- rescale output accumulators
        #pragma unroll
        for (int dt = 0; dt < 8; dt++) {
            oacc[dt][0] *= corr0; oacc[dt][1] *= corr0;
            oacc[dt][2] *= corr1; oacc[dt][3] *= corr1;
        }

        // ---- O += P . V
        #pragma unroll
        for (int kg = 0; kg < 2; kg++) {
            const uint32_t koff = kg * (16 * KVSTR * 2);
            uint32_t bv[4][4];
            #pragma unroll
            for (int dtp = 0; dtp < 4; dtp++)
                ldm_x4t(bv[dtp], addrV[dtp] + koff);
            #pragma unroll
            for (int dt = 0; dt < 8; dt++)
                mma_f16(oacc[dt], pa[kg], &bv[dt >> 1][(dt & 1) * 2]);
        }
        __syncthreads();
    }

    // ---- write y (fp16)
    const float inv0 = 1.f / l0, inv1 = 1.f / l1;
    __half2* yp0 = reinterpret_cast<__half2*>(&y[(rowbase + rg0) * C_ + h * D_]);
    __half2* yp1 = reinterpret_cast<__half2*>(&y[(rowbase + rg1) * C_ + h * D_]);
    #pragma unroll
    for (int dt = 0; dt < 8; dt++) {
        yp0[4 * dt + t] = __floats2half2_rn(oacc[dt][0] * inv0, oacc[dt][1] * inv0);
        yp1[4 * dt + t] = __floats2half2_rn(oacc[dt][2] * inv1, oacc[dt][3] * inv1);
    }
}

// ---------------------------------------------------------------------------
extern "C" void kernel_launch(void* const* d_in, const int* in_sizes, int n_in,
                              void* d_out, int out_size)
{
    const float* x      = (const float*)d_in[0];   // [2,2048,1024]
    const float* w_qkv  = (const float*)d_in[1];   // [1024,3072]
    const float* w_proj = (const float*)d_in[2];   // [1024,1024]
    const float* sink   = (const float*)d_in[3];   // [16]
    float* out = (float*)d_out;                    // [4096,1024]

    __half *qkv, *yb;
    cudaGetSymbolAddress((void**)&qkv, g_qkv);
    cudaGetSymbolAddress((void**)&yb,  g_y);

    // 1) qkv = x @ w_qkv  (fp32 in, fp16 out)
    gemm_f16<float, __half><<<dim3(QKVN / 128, M_ / 128), 256>>>(
        x, w_qkv, qkv, M_, QKVN, C_);
    // 2) attention (causal + sink), fp16 in/out
    attn_f16<<<dim3(T_ / 64, B_ * H_), 128>>>(qkv, sink, yb);
    // 3) out = y @ w_proj  (fp16 A, fp32 out)
    gemm_f16<__half, float><<<dim3(C_ / 128, M_ / 128), 256>>>(
        yb, w_proj, out, M_, C_, C_);
}

// round 5
// speedup vs baseline: 6.5897x; 1.0466x over previous
#include <cuda_runtime.h>
#include <cuda_fp16.h>
#include <math.h>
#include <stdint.h>

// Problem constants
#define B_    2
#define T_    2048
#define C_    1024
#define H_    16
#define D_    64
#define M_    (B_ * T_)          // 4096
#define QKVN  (3 * H_ * D_)      // 3072

// Scratch (allocation-free rule: device globals) — fp16
__device__ __half g_xh [(size_t)M_ * C_];      // x in fp16
__device__ __half g_wqT[(size_t)QKVN * C_];    // w_qkv^T  [3072,1024]
__device__ __half g_wpT[(size_t)C_ * C_];      // w_proj^T [1024,1024]
__device__ __half g_qkv[(size_t)M_ * QKVN];
__device__ __half g_y  [(size_t)M_ * C_];

// ---------------------------------------------------------------------------
// helpers
// ---------------------------------------------------------------------------
__device__ __forceinline__ uint32_t pack2(float x, float y) {
    __half2 h = __floats2half2_rn(x, y);
    return *reinterpret_cast<uint32_t*>(&h);
}
__device__ __forceinline__ void mma_f16(float c[4], const uint32_t a[4],
                                        const uint32_t b[2]) {
    asm volatile(
        "mma.sync.aligned.m16n8k16.row.col.f32.f16.f16.f32 "
        "{%0,%1,%2,%3}, {%4,%5,%6,%7}, {%8,%9}, {%0,%1,%2,%3};\n"
        : "+f"(c[0]), "+f"(c[1]), "+f"(c[2]), "+f"(c[3])
        : "r"(a[0]), "r"(a[1]), "r"(a[2]), "r"(a[3]), "r"(b[0]), "r"(b[1]));
}
__device__ __forceinline__ void ldm_x4(uint32_t r[4], uint32_t addr) {
    asm volatile("ldmatrix.sync.aligned.m8n8.x4.shared.b16 {%0,%1,%2,%3}, [%4];"
        : "=r"(r[0]), "=r"(r[1]), "=r"(r[2]), "=r"(r[3]) : "r"(addr));
}
__device__ __forceinline__ void ldm_x4t(uint32_t r[4], uint32_t addr) {
    asm volatile("ldmatrix.sync.aligned.m8n8.x4.trans.shared.b16 {%0,%1,%2,%3}, [%4];"
        : "=r"(r[0]), "=r"(r[1]), "=r"(r[2]), "=r"(r[3]) : "r"(addr));
}
__device__ __forceinline__ void cpa16(uint32_t dst, const void* src) {
    asm volatile("cp.async.cg.shared.global [%0], [%1], 16;\n" :: "r"(dst), "l"(src));
}
#define CP_COMMIT() asm volatile("cp.async.commit_group;" ::: "memory")
#define CP_WAIT0()  asm volatile("cp.async.wait_group 0;"  ::: "memory")
#define CP_WAIT1()  asm volatile("cp.async.wait_group 1;"  ::: "memory")
#define CP_WAIT2()  asm volatile("cp.async.wait_group 2;"  ::: "memory")

// FMA-only exp2 for t <= 0 (no MUFU).  ~4e-5 max rel error.
__device__ __forceinline__ float exp2_fast(float t) {
    t = fmaxf(t, -120.f);
    float r = rintf(t);
    float f = t - r;
    float p = fmaf(f, 0.009618129f, 0.055504109f);
    p = fmaf(f, p, 0.240226507f);
    p = fmaf(f, p, 0.693147181f);
    p = fmaf(f, p, 1.0f);
    return __int_as_float(__float_as_int(p) + (((int)r) << 23));
}

// ---------------------------------------------------------------------------
// pre-pass kernels
// ---------------------------------------------------------------------------
__global__ void convert_x(const float* __restrict__ x, __half* __restrict__ xh,
                          int n4) {
    int i = blockIdx.x * blockDim.x + threadIdx.x;
    if (i < n4) {
        float4 v = reinterpret_cast<const float4*>(x)[i];
        reinterpret_cast<uint2*>(xh)[i] = make_uint2(pack2(v.x, v.y), pack2(v.z, v.w));
    }
}
// wt[n][k] = (half) w[k][n];  w: [K,N] fp32 row-major
__global__ void transpose_w(const float* __restrict__ w, __half* __restrict__ wt,
                            int K, int N) {
    __shared__ __half t[32][33];
    const int n0 = blockIdx.x * 32, k0 = blockIdx.y * 32;
    const int tx = threadIdx.x, ty = threadIdx.y;
    #pragma unroll
    for (int j = 0; j < 32; j += 8)
        t[ty + j][tx] = __float2half(w[(size_t)(k0 + ty + j) * N + n0 + tx]);
    __syncthreads();
    #pragma unroll
    for (int j = 0; j < 32; j += 8)
        wt[(size_t)(n0 + ty + j) * K + k0 + tx] = t[tx][ty + j];
}

// ---------------------------------------------------------------------------
// gemm_cp: C[M,N] = A[M,K] @ Bt[N,K]^T, A/Bt fp16 K-major.
// 128x128 tile, BK=32, 4-stage cp.async, 256 threads (8 warps 4x2),
// warp tile 32x64, mma.m16n8k16.f16 + non-trans ldmatrix for A and B.
// Both smem tiles 128 rows x 32 halves, stride 40 halves (80B, odd x 16B).
// ---------------------------------------------------------------------------
#define GSTAGE 20480                    // A tile 10240B + B tile 10240B
#define GEMM_SMEM (4 * GSTAGE)

template <typename TC>
__global__ __launch_bounds__(256, 2) void gemm_cp(
    const __half* __restrict__ A, const __half* __restrict__ Bt,
    TC* __restrict__ Cm, int M, int N, int K)
{
    extern __shared__ __align__(128) char smem[];
    uint32_t sb;
    asm("{ .reg .u64 t; cvta.to.shared.u64 t, %1; cvt.u32.u64 %0, t; }"
        : "=r"(sb) : "l"(smem));

    const int tid  = threadIdx.x;
    const int lane = tid & 31;
    const int warp = tid >> 5;
    const int wm = warp >> 1, wn = warp & 1;
    const int g = lane >> 2, t = lane & 3;
    const int m0 = blockIdx.y * 128;
    const int n0 = blockIdx.x * 128;
    const int nk = K >> 5;              // 32-K chunks

    const __half* Abase = A + (size_t)m0 * K;
    const __half* Bbase = Bt + (size_t)n0 * K;

    // cp.async mapping: 512 chunks each for A and B; 2+2 per thread
    const int r0c = tid >> 1, c0c = (tid & 1) * 2;       // rows 0..127, chunk pairs
    // per thread: A rows r0c (chunks c0c, c0c+1); B same

    auto load_chunk = [&](int c, int s) {
        const uint32_t base = sb + s * GSTAGE;
        const __half* Ac = Abase + (size_t)c * 32;
        const __half* Bc = Bbase + (size_t)c * 32;
        #pragma unroll
        for (int i = 0; i < 2; i++) {
            const uint32_t off = (uint32_t)r0c * 80 + (c0c + i) * 16;
            cpa16(base + off,         Ac + (size_t)r0c * K + (c0c + i) * 8);
            cpa16(base + 10240 + off, Bc + (size_t)r0c * K + (c0c + i) * 8);
        }
        CP_COMMIT();
    };

    // ldmatrix fragment addresses (stage 0)
    uint32_t aAddr[2], bAddr[4];
    #pragma unroll
    for (int mt = 0; mt < 2; mt++)
        aAddr[mt] = sb + (wm * 32 + mt * 16 + (lane & 15)) * 80
                       + ((lane >> 4) * 8) * 2;
    #pragma unroll
    for (int ntp = 0; ntp < 4; ntp++)
        bAddr[ntp] = sb + 10240
                   + (wn * 64 + ntp * 16 + ((lane >> 4) & 1) * 8 + (lane & 7)) * 80
                   + (((lane >> 3) & 1) * 8) * 2;

    load_chunk(0, 0); load_chunk(1, 1); load_chunk(2, 2);

    float acc[2][8][4];
    #pragma unroll
    for (int mt = 0; mt < 2; mt++)
        #pragma unroll
        for (int nt = 0; nt < 8; nt++)
            #pragma unroll
            for (int j = 0; j < 4; j++) acc[mt][nt][j] = 0.f;

    for (int kt = 0; kt < nk; kt++) {
        const int s = kt & 3;
        if (kt < nk - 2)      CP_WAIT2();
        else if (kt == nk - 2) CP_WAIT1();
        else                   CP_WAIT0();
        __syncthreads();
        if (kt + 3 < nk) load_chunk(kt + 3, (kt + 3) & 3);

        const uint32_t so = (uint32_t)s * GSTAGE;
        #pragma unroll
        for (int kk = 0; kk < 2; kk++) {       // two k16 steps
            const uint32_t ko = kk * 32;       // 16 halves = 32B
            uint32_t af[2][4], bf[4][4];
            ldm_x4(af[0], aAddr[0] + so + ko);
            ldm_x4(af[1], aAddr[1] + so + ko);
            #pragma unroll
            for (int ntp = 0; ntp < 4; ntp++)
                ldm_x4(bf[ntp], bAddr[ntp] + so + ko);
            #pragma unroll
            for (int mt = 0; mt < 2; mt++)
                #pragma unroll
                for (int nt = 0; nt < 8; nt++)
                    mma_f16(acc[mt][nt], af[mt], &bf[nt >> 1][(nt & 1) * 2]);
        }
        __syncthreads();
    }

    // epilogue
    #pragma unroll
    for (int mt = 0; mt < 2; mt++) {
        const int r0 = m0 + wm * 32 + mt * 16 + g;
        #pragma unroll
        for (int nt = 0; nt < 8; nt++) {
            const int c0 = n0 + wn * 64 + nt * 8 + 2 * t;
            if (sizeof(TC) == 2) {
                *reinterpret_cast<__half2*>((__half*)Cm + (size_t)r0 * N + c0) =
                    __floats2half2_rn(acc[mt][nt][0], acc[mt][nt][1]);
                *reinterpret_cast<__half2*>((__half*)Cm + (size_t)(r0 + 8) * N + c0) =
                    __floats2half2_rn(acc[mt][nt][2], acc[mt][nt][3]);
            } else {
                *reinterpret_cast<float2*>((float*)Cm + (size_t)r0 * N + c0) =
                    make_float2(acc[mt][nt][0], acc[mt][nt][1]);
                *reinterpret_cast<float2*>((float*)Cm + (size_t)(r0 + 8) * N + c0) =
                    make_float2(acc[mt][nt][2], acc[mt][nt][3]);
            }
        }
    }
}

// ---------------------------------------------------------------------------
// attn_f16: tensor-core flash attention, log2-domain softmax (no MUFU),
// 3-stage cp.async KV ring, sink logit, P in registers.
// Grid (T/64, B*H), 128 threads = 4 warps; warp owns 16 query rows.
// ---------------------------------------------------------------------------
#define KVSTR 72                       // halves per KV row (144B, odd x 16B)
#define KVTILE (32 * KVSTR)            // halves per tile
#define KVSTAGE_B (2 * KVTILE * 2)     // bytes per stage (K + V)

__global__ __launch_bounds__(128) void attn_f16(
    const __half* __restrict__ qkv, const float* __restrict__ sink,
    __half* __restrict__ y)
{
    __shared__ __align__(16) __half KV[3][2][KVTILE];

    const int tid  = threadIdx.x;
    const int lane = tid & 31;
    const int warp = tid >> 5;
    const int g = lane >> 2, t = lane & 3;
    const int qt = (int)gridDim.x - 1 - (int)blockIdx.x;   // longest first
    const int bh = blockIdx.y;
    const int b = bh >> 4, h = bh & 15;
    const int q0 = qt * 64;
    const size_t rowbase = (size_t)b * T_;

    const int rg0 = q0 + warp * 16 + g;
    const int rg1 = rg0 + 8;

    // Q fragments, scale = (1/8)*log2(e) folded in (log2-domain scores)
    uint32_t qa[4][4];
    {
        const __half2 sc = __floats2half2_rn(0.18033688f, 0.18033688f);
        const __half2* qp0 = reinterpret_cast<const __half2*>(
            &qkv[(rowbase + rg0) * QKVN + h * D_]);
        const __half2* qp8 = qp0 + (size_t)8 * QKVN / 2;
        #pragma unroll
        for (int ks = 0; ks < 4; ks++) {
            __half2 v0 = __hmul2(qp0[8 * ks + t], sc);
            __half2 v1 = __hmul2(qp8[8 * ks + t], sc);
            __half2 v2 = __hmul2(qp0[8 * ks + t + 4], sc);
            __half2 v3 = __hmul2(qp8[8 * ks + t + 4], sc);
            qa[ks][0] = *reinterpret_cast<uint32_t*>(&v0);
            qa[ks][1] = *reinterpret_cast<uint32_t*>(&v1);
            qa[ks][2] = *reinterpret_cast<uint32_t*>(&v2);
            qa[ks][3] = *reinterpret_cast<uint32_t*>(&v3);
        }
    }

    // ldmatrix base addresses (stage 0)
    uint32_t addrK[2], addrV[4];
    {
        uint32_t base = (uint32_t)__cvta_generic_to_shared(&KV[0][0][0]);
        const int kvK = ((lane >> 4) & 1) * 8 + (lane & 7);
        const int dK  = ((lane >> 3) & 1) * 8;
        addrK[0] = base + (kvK * KVSTR + dK) * 2;
        addrK[1] = addrK[0] + 16 * KVSTR * 2;
        uint32_t vbase = base + KVTILE * 2;
        const int kvV = ((lane >> 3) & 1) * 8 + (lane & 7);
        #pragma unroll
        for (int dtp = 0; dtp < 4; dtp++) {
            const int dV = dtp * 16 + ((lane >> 4) & 1) * 8;
            addrV[dtp] = vbase + (kvV * KVSTR + dV) * 2;
        }
    }

    // KV tile loader: tile j -> stage s (cp.async, 4x16B per thread)
    auto load_kv = [&](int j, int s) {
        uint32_t base = (uint32_t)__cvta_generic_to_shared(&KV[s][0][0]);
        const int j0 = j * 32;
        #pragma unroll
        for (int i = 0; i < 4; i++) {
            const int id = tid + 128 * i;          // 0..511
            const int kv = (id >> 8) & 1;          // 0 = K, 1 = V
            const int r  = (id & 255) >> 3;
            const int c16 = id & 7;
            const size_t src = (rowbase + j0 + r) * QKVN
                             + (size_t)(1 + kv) * H_ * D_ + h * D_ + c16 * 8;
            cpa16(base + kv * (KVTILE * 2) + r * (KVSTR * 2) + c16 * 16,
                  &qkv[src]);
        }
        CP_COMMIT();
    };

    // online softmax state in log2 domain (sink: m = sink*log2e, l = 1)
    float m0v = sink[h] * 1.44269504f, m1v = m0v;
    float l0 = 1.f, l1 = 1.f;
    float oacc[8][4];
    #pragma unroll
    for (int dt = 0; dt < 8; dt++)
        #pragma unroll
        for (int j = 0; j < 4; j++) oacc[dt][j] = 0.f;

    const int ntile = (q0 >> 5) + 2;
    load_kv(0, 0);
    load_kv(1, 1);

    for (int j = 0; j < ntile; j++) {
        const int s = j % 3;
        if (j < ntile - 1) CP_WAIT1(); else CP_WAIT0();
        __syncthreads();
        if (j + 2 < ntile) load_kv(j + 2, (j + 2) % 3);

        const uint32_t so = (uint32_t)s * KVSTAGE_B;

        // S (log2 domain) = (Q*scale*log2e) . K^T
        float sacc[4][4];
        #pragma unroll
        for (int nt = 0; nt < 4; nt++)
            #pragma unroll
            for (int jj = 0; jj < 4; jj++) sacc[nt][jj] = 0.f;
        #pragma unroll
        for (int ks = 0; ks < 4; ks++) {
            uint32_t bk0[4], bk1[4];
            ldm_x4(bk0, addrK[0] + so + ks * 32);
            ldm_x4(bk1, addrK[1] + so + ks * 32);
            mma_f16(sacc[0], qa[ks], &bk0[0]);
            mma_f16(sacc[1], qa[ks], &bk0[2]);
            mma_f16(sacc[2], qa[ks], &bk1[0]);
            mma_f16(sacc[3], qa[ks], &bk1[2]);
        }

        // causal mask (last two tiles only)
        const int j0 = j * 32;
        if (j0 >= q0) {
            #pragma unroll
            for (int nt = 0; nt < 4; nt++) {
                const int cg = j0 + nt * 8 + 2 * t;
                if (cg     > rg0) sacc[nt][0] = -1e30f;
                if (cg + 1 > rg0) sacc[nt][1] = -1e30f;
                if (cg     > rg1) sacc[nt][2] = -1e30f;
                if (cg + 1 > rg1) sacc[nt][3] = -1e30f;
            }
        }

        // row maxima
        float rmax0 = -1e30f, rmax1 = -1e30f;
        #pragma unroll
        for (int nt = 0; nt < 4; nt++) {
            rmax0 = fmaxf(rmax0, fmaxf(sacc[nt][0], sacc[nt][1]));
            rmax1 = fmaxf(rmax1, fmaxf(sacc[nt][2], sacc[nt][3]));
        }
        rmax0 = fmaxf(rmax0, __shfl_xor_sync(0xffffffffu, rmax0, 1));
        rmax0 = fmaxf(rmax0, __shfl_xor_sync(0xffffffffu, rmax0, 2));
        rmax1 = fmaxf(rmax1, __shfl_xor_sync(0xffffffffu, rmax1, 1));
        rmax1 = fmaxf(rmax1, __shfl_xor_sync(0xffffffffu, rmax1, 2));

        const float mn0 = fmaxf(m0v, rmax0);
        const float mn1 = fmaxf(m1v, rmax1);
        const float corr0 = exp2_fast(m0v - mn0);
        const float corr1 = exp2_fast(m1v - mn1);
        m0v = mn0; m1v = mn1;

        // P = 2^(S - m)  (FMA-only)
        float p[4][4];
        float ps0 = 0.f, ps1 = 0.f;
        #pragma unroll
        for (int nt = 0; nt < 4; nt++) {
            p[nt][0] = exp2_fast(sacc[nt][0] - mn0);
            p[nt][1] = exp2_fast(sacc[nt][1] - mn0);
            p[nt][2] = exp2_fast(sacc[nt][2] - mn1);
            p[nt][3] = exp2_fast(sacc[nt][3] - mn1);
            ps0 += p[nt][0] + p[nt][1];
            ps1 += p[nt][2] + p[nt][3];
        }
        ps0 += __shfl_xor_sync(0xffffffffu, ps0, 1);
        ps0 += __shfl_xor_sync(0xffffffffu, ps0, 2);
        ps1 += __shfl_xor_sync(0xffffffffu, ps1, 1);
        ps1 += __shfl_xor_sync(0xffffffffu, ps1, 2);
        l0 = l0 * corr0 + ps0;
        l1 = l1 * corr1 + ps1;

        uint32_t pa[2][4];
        #pragma unroll
        for (int kg = 0; kg < 2; kg++) {
            pa[kg][0] = pack2(p[kg * 2][0], p[kg * 2][1]);
            pa[kg][1] = pack2(p[kg * 2][2], p[kg * 2][3]);
            pa[kg][2] = pack2(p[kg * 2 + 1][0], p[kg * 2 + 1][1]);
            pa[kg][3] = pack2(p[kg * 2 + 1][2], p[kg * 2 + 1][3]);
        }

        #pragma unroll
        for (int dt = 0; dt < 8; dt++) {
            oacc[dt][0] *= corr0; oacc[dt][1] *= corr0;
            oacc[dt][2] *= corr1; oacc[dt][3] *= corr1;
        }

        // O += P . V
        #pragma unroll
        for (int kg = 0; kg < 2; kg++) {
            const uint32_t koff = so + kg * (16 * KVSTR * 2);
            uint32_t bv[4][4];
            #pragma unroll
            for (int dtp = 0; dtp < 4; dtp++)
                ldm_x4t(bv[dtp], addrV[dtp] + koff);
            #pragma unroll
            for (int dt = 0; dt < 8; dt++)
                mma_f16(oacc[dt], pa[kg], &bv[dt >> 1][(dt & 1) * 2]);
        }
    }

    // write y (fp16)
    const float inv0 = 1.f / l0, inv1 = 1.f / l1;
    __half2* yp0 = reinterpret_cast<__half2*>(&y[(rowbase + rg0) * C_ + h * D_]);
    __half2* yp1 = reinterpret_cast<__half2*>(&y[(rowbase + rg1) * C_ + h * D_]);
    #pragma unroll
    for (int dt = 0; dt < 8; dt++) {
        yp0[4 * dt + t] = __floats2half2_rn(oacc[dt][0] * inv0, oacc[dt][1] * inv0);
        yp1[4 * dt + t] = __floats2half2_rn(oacc[dt][2] * inv1, oacc[dt][3] * inv1);
    }
}

// ---------------------------------------------------------------------------
extern "C" void kernel_launch(void* const* d_in, const int* in_sizes, int n_in,
                              void* d_out, int out_size)
{
    const float* x      = (const float*)d_in[0];   // [2,2048,1024]
    const float* w_qkv  = (const float*)d_in[1];   // [1024,3072]
    const float* w_proj = (const float*)d_in[2];   // [1024,1024]
    const float* sink   = (const float*)d_in[3];   // [16]
    float* out = (float*)d_out;                    // [4096,1024]

    __half *xh, *wqT, *wpT, *qkv, *yb;
    cudaGetSymbolAddress((void**)&xh,  g_xh);
    cudaGetSymbolAddress((void**)&wqT, g_wqT);
    cudaGetSymbolAddress((void**)&wpT, g_wpT);
    cudaGetSymbolAddress((void**)&qkv, g_qkv);
    cudaGetSymbolAddress((void**)&yb,  g_y);

    cudaFuncSetAttribute(gemm_cp<__half>,
        cudaFuncAttributeMaxDynamicSharedMemorySize, GEMM_SMEM);
    cudaFuncSetAttribute(gemm_cp<float>,
        cudaFuncAttributeMaxDynamicSharedMemorySize, GEMM_SMEM);

    // 0) pre-pass: fp16 conversions + weight transposes
    convert_x<<<(M_ * C_ / 4 + 255) / 256, 256>>>(x, xh, M_ * C_ / 4);
    transpose_w<<<dim3(QKVN / 32, C_ / 32), dim3(32, 8)>>>(w_qkv, wqT, C_, QKVN);
    transpose_w<<<dim3(C_ / 32, C_ / 32), dim3(32, 8)>>>(w_proj, wpT, C_, C_);

    // 1) qkv = xh @ wqT^T
    gemm_cp<__half><<<dim3(QKVN / 128, M_ / 128), 256, GEMM_SMEM>>>(
        xh, wqT, qkv, M_, QKVN, C_);
    // 2) attention (causal + sink)
    attn_f16<<<dim3(T_ / 64, B_ * H_), 128>>>(qkv, sink, yb);
    // 3) out = y @ wpT^T (fp32 out)
    gemm_cp<float><<<dim3(C_ / 128, M_ / 128), 256, GEMM_SMEM>>>(
        yb, wpT, out, M_, C_, C_);
}

// round 7
// speedup vs baseline: 7.0081x; 1.0635x over previous
#include <cuda_runtime.h>
#include <cuda_fp16.h>
#include <math.h>
#include <stdint.h>

// Problem constants
#define B_    2
#define T_    2048
#define C_    1024
#define H_    16
#define D_    64
#define M_    (B_ * T_)          // 4096
#define QKVN  (3 * H_ * D_)      // 3072

// Scratch (allocation-free rule: device globals) — fp16
__device__ __half g_xh [(size_t)M_ * C_];      // x in fp16
__device__ __half g_wqT[(size_t)QKVN * C_];    // w_qkv^T  [3072,1024]
__device__ __half g_wpT[(size_t)C_ * C_];      // w_proj^T [1024,1024]
__device__ __half g_qkv[(size_t)M_ * QKVN];
__device__ __half g_y  [(size_t)M_ * C_];

// ---------------------------------------------------------------------------
// helpers
// ---------------------------------------------------------------------------
__device__ __forceinline__ uint32_t pack2(float x, float y) {
    __half2 h = __floats2half2_rn(x, y);
    return *reinterpret_cast<uint32_t*>(&h);
}
__device__ __forceinline__ void mma_f16(float c[4], const uint32_t a[4],
                                        const uint32_t b[2]) {
    asm volatile(
        "mma.sync.aligned.m16n8k16.row.col.f32.f16.f16.f32 "
        "{%0,%1,%2,%3}, {%4,%5,%6,%7}, {%8,%9}, {%0,%1,%2,%3};\n"
        : "+f"(c[0]), "+f"(c[1]), "+f"(c[2]), "+f"(c[3])
        : "r"(a[0]), "r"(a[1]), "r"(a[2]), "r"(a[3]), "r"(b[0]), "r"(b[1]));
}
__device__ __forceinline__ void ldm_x4(uint32_t r[4], uint32_t addr) {
    asm volatile("ldmatrix.sync.aligned.m8n8.x4.shared.b16 {%0,%1,%2,%3}, [%4];"
        : "=r"(r[0]), "=r"(r[1]), "=r"(r[2]), "=r"(r[3]) : "r"(addr));
}
__device__ __forceinline__ void ldm_x4t(uint32_t r[4], uint32_t addr) {
    asm volatile("ldmatrix.sync.aligned.m8n8.x4.trans.shared.b16 {%0,%1,%2,%3}, [%4];"
        : "=r"(r[0]), "=r"(r[1]), "=r"(r[2]), "=r"(r[3]) : "r"(addr));
}
__device__ __forceinline__ void cpa16(uint32_t dst, const void* src) {
    asm volatile("cp.async.cg.shared.global [%0], [%1], 16;\n" :: "r"(dst), "l"(src));
}
#define CP_COMMIT() asm volatile("cp.async.commit_group;" ::: "memory")
#define CP_WAIT0()  asm volatile("cp.async.wait_group 0;"  ::: "memory")
#define CP_WAIT1()  asm volatile("cp.async.wait_group 1;"  ::: "memory")
#define CP_WAIT2()  asm volatile("cp.async.wait_group 2;"  ::: "memory")

// FMA-only exp2 (no MUFU); clamps below -120.
__device__ __forceinline__ float exp2_fast(float t) {
    t = fmaxf(t, -120.f);
    float r = rintf(t);
    float f = t - r;
    float p = fmaf(f, 0.009618129f, 0.055504109f);
    p = fmaf(f, p, 0.240226507f);
    p = fmaf(f, p, 0.693147181f);
    p = fmaf(f, p, 1.0f);
    return __int_as_float(__float_as_int(p) + (((int)r) << 23));
}

// ---------------------------------------------------------------------------
// pre-pass kernels
// ---------------------------------------------------------------------------
__global__ void convert_x(const float* __restrict__ x, __half* __restrict__ xh,
                          int n4) {
    int i = blockIdx.x * blockDim.x + threadIdx.x;
    if (i < n4) {
        float4 v = reinterpret_cast<const float4*>(x)[i];
        reinterpret_cast<uint2*>(xh)[i] = make_uint2(pack2(v.x, v.y), pack2(v.z, v.w));
    }
}
// wt[n][k] = (half) w[k][n];  w: [K,N] fp32 row-major
__global__ void transpose_w(const float* __restrict__ w, __half* __restrict__ wt,
                            int K, int N) {
    __shared__ __half t[32][33];
    const int n0 = blockIdx.x * 32, k0 = blockIdx.y * 32;
    const int tx = threadIdx.x, ty = threadIdx.y;
    #pragma unroll
    for (int j = 0; j < 32; j += 8)
        t[ty + j][tx] = __float2half(w[(size_t)(k0 + ty + j) * N + n0 + tx]);
    __syncthreads();
    #pragma unroll
    for (int j = 0; j < 32; j += 8)
        wt[(size_t)(n0 + ty + j) * K + k0 + tx] = t[tx][ty + j];
}

// ---------------------------------------------------------------------------
// gemm_cp: C[M,N] = A[M,K] @ Bt[N,K]^T, fp16 K-major operands.
// 128x128 tile, BK=32, 4-stage cp.async, 256 threads (8 warps 4x2),
// warp tile 32x64, ONE __syncthreads per k-chunk.
// ---------------------------------------------------------------------------
#define GSTAGE 20480                    // A tile 10240B + B tile 10240B
#define GEMM_SMEM (4 * GSTAGE)

template <typename TC>
__global__ __launch_bounds__(256, 2) void gemm_cp(
    const __half* __restrict__ A, const __half* __restrict__ Bt,
    TC* __restrict__ Cm, int M, int N, int K)
{
    extern __shared__ __align__(128) char smem[];
    uint32_t sb;
    asm("{ .reg .u64 t; cvta.to.shared.u64 t, %1; cvt.u32.u64 %0, t; }"
        : "=r"(sb) : "l"(smem));

    const int tid  = threadIdx.x;
    const int lane = tid & 31;
    const int warp = tid >> 5;
    const int wm = warp >> 1, wn = warp & 1;
    const int g = lane >> 2, t = lane & 3;
    const int m0 = blockIdx.y * 128;
    const int n0 = blockIdx.x * 128;
    const int nk = K >> 5;

    const __half* Abase = A + (size_t)m0 * K;
    const __half* Bbase = Bt + (size_t)n0 * K;

    const int r0c = tid >> 1, c0c = (tid & 1) * 2;

    auto load_chunk = [&](int c, int s) {
        const uint32_t base = sb + s * GSTAGE;
        const __half* Ac = Abase + (size_t)c * 32;
        const __half* Bc = Bbase + (size_t)c * 32;
        #pragma unroll
        for (int i = 0; i < 2; i++) {
            const uint32_t off = (uint32_t)r0c * 80 + (c0c + i) * 16;
            cpa16(base + off,         Ac + (size_t)r0c * K + (c0c + i) * 8);
            cpa16(base + 10240 + off, Bc + (size_t)r0c * K + (c0c + i) * 8);
        }
        CP_COMMIT();
    };

    uint32_t aAddr[2], bAddr[4];
    #pragma unroll
    for (int mt = 0; mt < 2; mt++)
        aAddr[mt] = sb + (wm * 32 + mt * 16 + (lane & 15)) * 80
                       + ((lane >> 4) * 8) * 2;
    #pragma unroll
    for (int ntp = 0; ntp < 4; ntp++)
        bAddr[ntp] = sb + 10240
                   + (wn * 64 + ntp * 16 + ((lane >> 4) & 1) * 8 + (lane & 7)) * 80
                   + (((lane >> 3) & 1) * 8) * 2;

    load_chunk(0, 0); load_chunk(1, 1); load_chunk(2, 2);

    float acc[2][8][4];
    #pragma unroll
    for (int mt = 0; mt < 2; mt++)
        #pragma unroll
        for (int nt = 0; nt < 8; nt++)
            #pragma unroll
            for (int j = 0; j < 4; j++) acc[mt][nt][j] = 0.f;

    for (int kt = 0; kt < nk; kt++) {
        const int s = kt & 3;
        if (kt < nk - 2)       CP_WAIT2();
        else if (kt == nk - 2) CP_WAIT1();
        else                   CP_WAIT0();
        __syncthreads();                       // single barrier per chunk
        if (kt + 3 < nk) load_chunk(kt + 3, (kt + 3) & 3);

        const uint32_t so = (uint32_t)s * GSTAGE;
        #pragma unroll
        for (int kk = 0; kk < 2; kk++) {
            const uint32_t ko = kk * 32;
            uint32_t af[2][4], bf[4][4];
            ldm_x4(af[0], aAddr[0] + so + ko);
            ldm_x4(af[1], aAddr[1] + so + ko);
            #pragma unroll
            for (int ntp = 0; ntp < 4; ntp++)
                ldm_x4(bf[ntp], bAddr[ntp] + so + ko);
            #pragma unroll
            for (int mt = 0; mt < 2; mt++)
                #pragma unroll
                for (int nt = 0; nt < 8; nt++)
                    mma_f16(acc[mt][nt], af[mt], &bf[nt >> 1][(nt & 1) * 2]);
        }
    }

    #pragma unroll
    for (int mt = 0; mt < 2; mt++) {
        const int r0 = m0 + wm * 32 + mt * 16 + g;
        #pragma unroll
        for (int nt = 0; nt < 8; nt++) {
            const int c0 = n0 + wn * 64 + nt * 8 + 2 * t;
            if (sizeof(TC) == 2) {
                *reinterpret_cast<__half2*>((__half*)Cm + (size_t)r0 * N + c0) =
                    __floats2half2_rn(acc[mt][nt][0], acc[mt][nt][1]);
                *reinterpret_cast<__half2*>((__half*)Cm + (size_t)(r0 + 8) * N + c0) =
                    __floats2half2_rn(acc[mt][nt][2], acc[mt][nt][3]);
            } else {
                *reinterpret_cast<float2*>((float*)Cm + (size_t)r0 * N + c0) =
                    make_float2(acc[mt][nt][0], acc[mt][nt][1]);
                *reinterpret_cast<float2*>((float*)Cm + (size_t)(r0 + 8) * N + c0) =
                    make_float2(acc[mt][nt][2], acc[mt][nt][3]);
            }
        }
    }
}

// ---------------------------------------------------------------------------
// attn_f16: tensor-core flash attention, ONLINE softmax (log2 domain,
// FMA-only exp2), BKV=64 (per-tile reduction cost amortized over 2x keys),
// 3-stage cp.async KV ring (dynamic smem), sink logit, P in registers.
// Grid (T/64, B*H), 128 threads = 4 warps; warp owns 16 query rows.
// ---------------------------------------------------------------------------
#define KVSTR   72                      // halves per KV row (144B, odd x 16B)
#define KVROWS  64
#define KVTILE  (KVROWS * KVSTR)        // halves per K (or V) tile
#define KVSTAGE_B (2 * KVTILE * 2)      // bytes per stage (K + V) = 18432
#define ATTN_SMEM (3 * KVSTAGE_B)       // 55296

__global__ __launch_bounds__(128) void attn_f16(
    const __half* __restrict__ qkv, const float* __restrict__ sink,
    __half* __restrict__ y)
{
    extern __shared__ __align__(16) __half KV[];

    const int tid  = threadIdx.x;
    const int lane = tid & 31;
    const int warp = tid >> 5;
    const int g = lane >> 2, t = lane & 3;
    const int qt = (int)gridDim.x - 1 - (int)blockIdx.x;   // longest first
    const int bh = blockIdx.y;
    const int b = bh >> 4, h = bh & 15;
    const int q0 = qt * 64;
    const size_t rowbase = (size_t)b * T_;

    const int rg0 = q0 + warp * 16 + g;
    const int rg1 = rg0 + 8;

    // Q fragments, scale = (1/8)*log2(e) folded in (log2-domain scores)
    uint32_t qa[4][4];
    {
        const __half2 sc = __floats2half2_rn(0.18033688f, 0.18033688f);
        const __half2* qp0 = reinterpret_cast<const __half2*>(
            &qkv[(rowbase + rg0) * QKVN + h * D_]);
        const __half2* qp8 = qp0 + (size_t)8 * QKVN / 2;
        #pragma unroll
        for (int ks = 0; ks < 4; ks++) {
            __half2 v0 = __hmul2(qp0[8 * ks + t], sc);
            __half2 v1 = __hmul2(qp8[8 * ks + t], sc);
            __half2 v2 = __hmul2(qp0[8 * ks + t + 4], sc);
            __half2 v3 = __hmul2(qp8[8 * ks + t + 4], sc);
            qa[ks][0] = *reinterpret_cast<uint32_t*>(&v0);
            qa[ks][1] = *reinterpret_cast<uint32_t*>(&v1);
            qa[ks][2] = *reinterpret_cast<uint32_t*>(&v2);
            qa[ks][3] = *reinterpret_cast<uint32_t*>(&v3);
        }
    }

    // ldmatrix base addresses (stage 0)
    uint32_t sbase;
    asm("{ .reg .u64 tt; cvta.to.shared.u64 tt, %1; cvt.u32.u64 %0, tt; }"
        : "=r"(sbase) : "l"(KV));
    uint32_t addrK[4], addrV[4];
    {
        const int kvK = ((lane >> 4) & 1) * 8 + (lane & 7);
        const int dK  = ((lane >> 3) & 1) * 8;
        #pragma unroll
        for (int kg = 0; kg < 4; kg++)
            addrK[kg] = sbase + ((kvK + 16 * kg) * KVSTR + dK) * 2;
        const uint32_t vbase = sbase + KVTILE * 2;
        const int kvV = ((lane >> 3) & 1) * 8 + (lane & 7);
        #pragma unroll
        for (int dtp = 0; dtp < 4; dtp++) {
            const int dV = dtp * 16 + ((lane >> 4) & 1) * 8;
            addrV[dtp] = vbase + (kvV * KVSTR + dV) * 2;
        }
    }

    // KV tile loader: 64 rows x (K+V) = 16KB per stage, 8 x 16B per thread
    auto load_kv = [&](int j, int s) {
        const uint32_t base = sbase + (uint32_t)s * KVSTAGE_B;
        const int j0 = j * 64;
        #pragma unroll
        for (int i = 0; i < 8; i++) {
            const int id = tid + 128 * i;          // 0..1023
            const int kv = id >> 9;                // 0 = K, 1 = V
            const int r  = (id >> 3) & 63;
            const int c16 = id & 7;
            const size_t src = (rowbase + j0 + r) * QKVN
                             + (size_t)(1 + kv) * H_ * D_ + h * D_ + c16 * 8;
            cpa16(base + kv * (KVTILE * 2) + r * (KVSTR * 2) + c16 * 16,
                  &qkv[src]);
        }
        CP_COMMIT();
    };

    // online softmax state (log2 domain; sink: m = sink*log2e, l = 1)
    float m0v = sink[h] * 1.44269504f, m1v = m0v;
    float l0 = 1.f, l1 = 1.f;
    float oacc[8][4];
    #pragma unroll
    for (int dt = 0; dt < 8; dt++)
        #pragma unroll
        for (int j = 0; j < 4; j++) oacc[dt][j] = 0.f;

    const int ntile = qt + 1;
    load_kv(0, 0);
    if (ntile > 1) load_kv(1, 1);

    for (int j = 0; j < ntile; j++) {
        const int s = j % 3;
        if (j < ntile - 1) CP_WAIT1(); else CP_WAIT0();
        __syncthreads();
        if (j + 2 < ntile) load_kv(j + 2, (j + 2) % 3);

        const uint32_t so = (uint32_t)s * KVSTAGE_B;

        // S (log2 domain) = (Q*scale*log2e) . K^T   [16 x 64 per warp]
        float sacc[8][4];
        #pragma unroll
        for (int nt = 0; nt < 8; nt++)
            #pragma unroll
            for (int jj = 0; jj < 4; jj++) sacc[nt][jj] = 0.f;
        #pragma unroll
        for (int ks = 0; ks < 4; ks++) {
            #pragma unroll
            for (int kg = 0; kg < 4; kg++) {
                uint32_t bk[4];
                ldm_x4(bk, addrK[kg] + so + ks * 32);
                mma_f16(sacc[2 * kg],     qa[ks], &bk[0]);
                mma_f16(sacc[2 * kg + 1], qa[ks], &bk[2]);
            }
        }

        // causal mask (diagonal tile only)
        const int j0 = j * 64;
        if (j0 >= q0) {
            #pragma unroll
            for (int nt = 0; nt < 8; nt++) {
                const int cg = j0 + nt * 8 + 2 * t;
                if (cg     > rg0) sacc[nt][0] = -1e30f;
                if (cg + 1 > rg0) sacc[nt][1] = -1e30f;
                if (cg     > rg1) sacc[nt][2] = -1e30f;
                if (cg + 1 > rg1) sacc[nt][3] = -1e30f;
            }
        }

        // row maxima (in-thread + quad shfl)
        float rmax0 = -1e30f, rmax1 = -1e30f;
        #pragma unroll
        for (int nt = 0; nt < 8; nt++) {
            rmax0 = fmaxf(rmax0, fmaxf(sacc[nt][0], sacc[nt][1]));
            rmax1 = fmaxf(rmax1, fmaxf(sacc[nt][2], sacc[nt][3]));
        }
        rmax0 = fmaxf(rmax0, __shfl_xor_sync(0xffffffffu, rmax0, 1));
        rmax0 = fmaxf(rmax0, __shfl_xor_sync(0xffffffffu, rmax0, 2));
        rmax1 = fmaxf(rmax1, __shfl_xor_sync(0xffffffffu, rmax1, 1));
        rmax1 = fmaxf(rmax1, __shfl_xor_sync(0xffffffffu, rmax1, 2));

        const float mn0 = fmaxf(m0v, rmax0);
        const float mn1 = fmaxf(m1v, rmax1);
        const float corr0 = exp2_fast(m0v - mn0);
        const float corr1 = exp2_fast(m1v - mn1);
        m0v = mn0; m1v = mn1;

        // P = 2^(S - m) (FMA-only); pack directly into mma A-fragments
        uint32_t pa[4][4];
        float ps0 = 0.f, ps1 = 0.f;
        #pragma unroll
        for (int kg = 0; kg < 4; kg++) {
            #pragma unroll
            for (int nn = 0; nn < 2; nn++) {
                const int nt = kg * 2 + nn;
                const float p0 = exp2_fast(sacc[nt][0] - mn0);
                const float p1 = exp2_fast(sacc[nt][1] - mn0);
                const float p2 = exp2_fast(sacc[nt][2] - mn1);
                const float p3 = exp2_fast(sacc[nt][3] - mn1);
                ps0 += p0 + p1;
                ps1 += p2 + p3;
                pa[kg][nn * 2 + 0] = pack2(p0, p1);
                pa[kg][nn * 2 + 1] = pack2(p2, p3);
            }
        }
        ps0 += __shfl_xor_sync(0xffffffffu, ps0, 1);
        ps0 += __shfl_xor_sync(0xffffffffu, ps0, 2);
        ps1 += __shfl_xor_sync(0xffffffffu, ps1, 1);
        ps1 += __shfl_xor_sync(0xffffffffu, ps1, 2);
        l0 = l0 * corr0 + ps0;
        l1 = l1 * corr1 + ps1;

        // rescale output accumulators (once per 64 keys)
        #pragma unroll
        for (int dt = 0; dt < 8; dt++) {
            oacc[dt][0] *= corr0; oacc[dt][1] *= corr0;
            oacc[dt][2] *= corr1; oacc[dt][3] *= corr1;
        }

        // O += P . V
        #pragma unroll
        for (int kg = 0; kg < 4; kg++) {
            const uint32_t koff = so + kg * (16 * KVSTR * 2);
            uint32_t bv[4][4];
            #pragma unroll
            for (int dtp = 0; dtp < 4; dtp++)
                ldm_x4t(bv[dtp], addrV[dtp] + koff);
            #pragma unroll
            for (int dt = 0; dt < 8; dt++)
                mma_f16(oacc[dt], pa[kg], &bv[dt >> 1][(dt & 1) * 2]);
        }
    }

    // write y (fp16)
    const float inv0 = 1.f / l0, inv1 = 1.f / l1;
    __half2* yp0 = reinterpret_cast<__half2*>(&y[(rowbase + rg0) * C_ + h * D_]);
    __half2* yp1 = reinterpret_cast<__half2*>(&y[(rowbase + rg1) * C_ + h * D_]);
    #pragma unroll
    for (int dt = 0; dt < 8; dt++) {
        yp0[4 * dt + t] = __floats2half2_rn(oacc[dt][0] * inv0, oacc[dt][1] * inv0);
        yp1[4 * dt + t] = __floats2half2_rn(oacc[dt][2] * inv1, oacc[dt][3] * inv1);
    }
}

// ---------------------------------------------------------------------------
extern "C" void kernel_launch(void* const* d_in, const int* in_sizes, int n_in,
                              void* d_out, int out_size)
{
    const float* x      = (const float*)d_in[0];   // [2,2048,1024]
    const float* w_qkv  = (const float*)d_in[1];   // [1024,3072]
    const float* w_proj = (const float*)d_in[2];   // [1024,1024]
    const float* sink   = (const float*)d_in[3];   // [16]
    float* out = (float*)d_out;                    // [4096,1024]

    __half *xh, *wqT, *wpT, *qkv, *yb;
    cudaGetSymbolAddress((void**)&xh,  g_xh);
    cudaGetSymbolAddress((void**)&wqT, g_wqT);
    cudaGetSymbolAddress((void**)&wpT, g_wpT);
    cudaGetSymbolAddress((void**)&qkv, g_qkv);
    cudaGetSymbolAddress((void**)&yb,  g_y);

    cudaFuncSetAttribute(gemm_cp<__half>,
        cudaFuncAttributeMaxDynamicSharedMemorySize, GEMM_SMEM);
    cudaFuncSetAttribute(gemm_cp<float>,
        cudaFuncAttributeMaxDynamicSharedMemorySize, GEMM_SMEM);
    cudaFuncSetAttribute(attn_f16,
        cudaFuncAttributeMaxDynamicSharedMemorySize, ATTN_SMEM);

    convert_x<<<(M_ * C_ / 4 + 255) / 256, 256>>>(x, xh, M_ * C_ / 4);
    transpose_w<<<dim3(QKVN / 32, C_ / 32), dim3(32, 8)>>>(w_qkv, wqT, C_, QKVN);
    transpose_w<<<dim3(C_ / 32, C_ / 32), dim3(32, 8)>>>(w_proj, wpT, C_, C_);

    gemm_cp<__half><<<dim3(QKVN / 128, M_ / 128), 256, GEMM_SMEM>>>(
        xh, wqT, qkv, M_, QKVN, C_);
    attn_f16<<<dim3(T_ / 64, B_ * H_), 128, ATTN_SMEM>>>(qkv, sink, yb);
    gemm_cp<float><<<dim3(C_ / 128, M_ / 128), 256, GEMM_SMEM>>>(
        yb, wpT, out, M_, C_, C_);
}